// round 1
// baseline (speedup 1.0000x reference)
#include <cuda_runtime.h>
#include <cuda_bf16.h>

// Problem constants
#define Bn 4
#define Sn 2048
#define En 1024
#define Hn 16
#define Dn 64
#define BHn (Bn*Hn)     // 64
#define Mn  (Bn*Sn)     // 8192

// Scratch (allocation-free rule: __device__ globals)
__device__ float g_Q[(size_t)BHn * Sn * Dn];   // 32 MB
__device__ float g_K[(size_t)BHn * Sn * Dn];   // 32 MB
__device__ float g_V[(size_t)BHn * Sn * Dn];   // 32 MB
__device__ float g_ctx[(size_t)Mn * En];       // 32 MB

// ---------------------------------------------------------------------------
// Kernel 1: fused QKV projection.
// One block computes a [64 x 64] tile of Q/K/V for one (b,h,proj).
// Tiled GEMM: BM=64, BN=D=64, BK=16, 256 threads, 4x4 register tiles.
// ---------------------------------------------------------------------------
__global__ __launch_bounds__(256) void qkv_kernel(
    const float* __restrict__ x,
    const float* __restrict__ Wq, const float* __restrict__ bq,
    const float* __restrict__ Wk, const float* __restrict__ bk,
    const float* __restrict__ Wv, const float* __restrict__ bv)
{
    const int proj = blockIdx.z;          // 0=Q, 1=K, 2=V
    const int bh   = blockIdx.y;          // b*H + h
    const int b    = bh >> 4;
    const int h    = bh & 15;
    const int s0   = blockIdx.x * 64;

    const float* W;
    const float* bias;
    float* out;
    if (proj == 0)      { W = Wq; bias = bq; out = g_Q; }
    else if (proj == 1) { W = Wk; bias = bk; out = g_K; }
    else                { W = Wv; bias = bv; out = g_V; }
    W    += (size_t)h * En * Dn;
    bias += h * Dn;

    const float* xb = x + ((size_t)b * Sn + s0) * En;

    __shared__ float xs[64][16];
    __shared__ float ws[16][64];

    const int tid = threadIdx.x;
    const int tx  = tid & 15;
    const int ty  = tid >> 4;
    const int r0  = ty << 2;
    const int c0  = tx << 2;

    // loader indices
    const int lm = tid >> 2;           // 0..63
    const int lk = (tid & 3) << 2;     // 0,4,8,12
    const int wk = tid >> 4;           // 0..15 (row of ws)
    const int wn = (tid & 15) << 2;    // 0..60

    float acc[4][4] = {};

    for (int k0 = 0; k0 < En; k0 += 16) {
        // load x tile [64 x 16]
        float4 xv = *(const float4*)(xb + (size_t)lm * En + k0 + lk);
        xs[lm][lk + 0] = xv.x; xs[lm][lk + 1] = xv.y;
        xs[lm][lk + 2] = xv.z; xs[lm][lk + 3] = xv.w;
        // load W tile [16 x 64]  (W row e is contiguous in d)
        *(float4*)&ws[wk][wn] = *(const float4*)(W + (size_t)(k0 + wk) * Dn + wn);
        __syncthreads();

        #pragma unroll
        for (int q = 0; q < 16; q++) {
            float4 bv4 = *(float4*)&ws[q][c0];
            #pragma unroll
            for (int i = 0; i < 4; i++) {
                float a = xs[r0 + i][q];
                acc[i][0] += a * bv4.x; acc[i][1] += a * bv4.y;
                acc[i][2] += a * bv4.z; acc[i][3] += a * bv4.w;
            }
        }
        __syncthreads();
    }

    float4 bb = *(const float4*)(bias + c0);
    float* ob = out + ((size_t)bh * Sn + s0) * Dn;
    #pragma unroll
    for (int i = 0; i < 4; i++) {
        float4 o;
        o.x = acc[i][0] + bb.x; o.y = acc[i][1] + bb.y;
        o.z = acc[i][2] + bb.z; o.w = acc[i][3] + bb.w;
        *(float4*)(ob + (size_t)(r0 + i) * Dn + c0) = o;
    }
}

// ---------------------------------------------------------------------------
// Kernel 2: causal flash attention per (b,h), 64-query tile per block.
// Online softmax with shuffle row-reductions; P staged through smem for PV.
// Writes ctx in concat layout [B, S, H*D].
// ---------------------------------------------------------------------------
__global__ __launch_bounds__(256) void attn_kernel(float* __restrict__ ctx)
{
    const int bh = blockIdx.y;
    const int b  = bh >> 4;
    const int h  = bh & 15;
    // reverse order: heaviest (largest i0) query tiles launch first
    const int i0 = (gridDim.x - 1 - blockIdx.x) * 64;

    const float* Qp = g_Q + (size_t)bh * Sn * Dn;
    const float* Kp = g_K + (size_t)bh * Sn * Dn;
    const float* Vp = g_V + (size_t)bh * Sn * Dn;

    __shared__ float Qs [64][64];
    __shared__ float KsT[64][68];   // transposed keys, padded
    __shared__ float Vs [64][64];
    __shared__ float Ps [64][68];   // probs, padded

    const int tid = threadIdx.x;
    const int tx  = tid & 15;
    const int ty  = tid >> 4;
    const int r0  = ty << 2;
    const int c0  = tx << 2;

    // load Q tile [64 x 64]
    {
        int row = tid >> 2;
        int col = (tid & 3) << 2;
        #pragma unroll
        for (int t = 0; t < 4; t++) {
            *(float4*)&Qs[row][col + t * 16] =
                *(const float4*)(Qp + (size_t)(i0 + row) * Dn + col + t * 16);
        }
    }

    float m[4], l[4], acc[4][4] = {};
    #pragma unroll
    for (int i = 0; i < 4; i++) { m[i] = -1e30f; l[i] = 0.f; }

    const float scale = 0.125f;   // 1/sqrt(64)

    for (int j0 = 0; j0 <= i0; j0 += 64) {
        __syncthreads();   // previous PV done before overwriting KsT/Vs
        // load K (transposed) and V tiles
        {
            int c  = tid >> 2;
            int d0 = (tid & 3) << 2;
            #pragma unroll
            for (int t = 0; t < 4; t++) {
                int d = d0 + t * 16;
                float4 kv = *(const float4*)(Kp + (size_t)(j0 + c) * Dn + d);
                KsT[d + 0][c] = kv.x; KsT[d + 1][c] = kv.y;
                KsT[d + 2][c] = kv.z; KsT[d + 3][c] = kv.w;
                *(float4*)&Vs[c][d] = *(const float4*)(Vp + (size_t)(j0 + c) * Dn + d);
            }
        }
        __syncthreads();

        // S = Q K^T (4x4 per thread)
        float s[4][4] = {};
        #pragma unroll 8
        for (int d = 0; d < 64; d++) {
            float4 k4 = *(float4*)&KsT[d][c0];
            #pragma unroll
            for (int i = 0; i < 4; i++) {
                float a = Qs[r0 + i][d];
                s[i][0] += a * k4.x; s[i][1] += a * k4.y;
                s[i][2] += a * k4.z; s[i][3] += a * k4.w;
            }
        }

        // scale + causal mask (only the diagonal tile needs masking)
        const bool diag = (j0 == i0);
        #pragma unroll
        for (int i = 0; i < 4; i++)
            #pragma unroll
            for (int j = 0; j < 4; j++) {
                s[i][j] *= scale;
                if (diag && (c0 + j) > (r0 + i)) s[i][j] = -1e30f;
            }

        // online softmax (row reduce across the 16 tx lanes via shfl)
        #pragma unroll
        for (int i = 0; i < 4; i++) {
            float rm = fmaxf(fmaxf(s[i][0], s[i][1]), fmaxf(s[i][2], s[i][3]));
            #pragma unroll
            for (int off = 1; off < 16; off <<= 1)
                rm = fmaxf(rm, __shfl_xor_sync(0xffffffffu, rm, off));
            float nm   = fmaxf(m[i], rm);
            float corr = __expf(m[i] - nm);
            float rs = 0.f;
            #pragma unroll
            for (int j = 0; j < 4; j++) { s[i][j] = __expf(s[i][j] - nm); rs += s[i][j]; }
            #pragma unroll
            for (int off = 1; off < 16; off <<= 1)
                rs += __shfl_xor_sync(0xffffffffu, rs, off);
            l[i] = l[i] * corr + rs;
            m[i] = nm;
            #pragma unroll
            for (int j = 0; j < 4; j++) acc[i][j] *= corr;
        }

        // stage P to smem
        #pragma unroll
        for (int i = 0; i < 4; i++)
            *(float4*)&Ps[r0 + i][c0] = make_float4(s[i][0], s[i][1], s[i][2], s[i][3]);
        __syncthreads();

        // O += P @ V
        #pragma unroll 8
        for (int k = 0; k < 64; k++) {
            float4 v4 = *(float4*)&Vs[k][c0];
            #pragma unroll
            for (int i = 0; i < 4; i++) {
                float p = Ps[r0 + i][k];
                acc[i][0] += p * v4.x; acc[i][1] += p * v4.y;
                acc[i][2] += p * v4.z; acc[i][3] += p * v4.w;
            }
        }
    }

    // normalize and write ctx[b][s][h*D + d]
    float* cb = ctx + ((size_t)b * Sn + i0) * En + h * Dn;
    #pragma unroll
    for (int i = 0; i < 4; i++) {
        float inv = 1.f / l[i];
        float4 o = make_float4(acc[i][0] * inv, acc[i][1] * inv,
                               acc[i][2] * inv, acc[i][3] * inv);
        *(float4*)(cb + (size_t)(r0 + i) * En + c0) = o;
    }
}

// ---------------------------------------------------------------------------
// Kernel 3: output projection  out = ctx @ Wo^T + bo
// ctx [M=8192, K=1024], Wo [N=1024, K=1024] (row-major, K contiguous)
// ---------------------------------------------------------------------------
__global__ __launch_bounds__(256) void oproj_kernel(
    const float* __restrict__ Wo, const float* __restrict__ bo,
    float* __restrict__ out)
{
    const int m0 = blockIdx.x * 64;
    const int n0 = blockIdx.y * 64;

    __shared__ float as[64][16];
    __shared__ float ws[16][68];   // transposed Wo tile, padded

    const int tid = threadIdx.x;
    const int tx  = tid & 15;
    const int ty  = tid >> 4;
    const int r0  = ty << 2;
    const int c0  = tx << 2;

    const int lm = tid >> 2;          // 0..63
    const int lk = (tid & 3) << 2;    // 0,4,8,12

    float acc[4][4] = {};

    for (int k0 = 0; k0 < En; k0 += 16) {
        float4 av = *(const float4*)(g_ctx + (size_t)(m0 + lm) * En + k0 + lk);
        as[lm][lk + 0] = av.x; as[lm][lk + 1] = av.y;
        as[lm][lk + 2] = av.z; as[lm][lk + 3] = av.w;

        float4 wv = *(const float4*)(Wo + (size_t)(n0 + lm) * En + k0 + lk);
        ws[lk + 0][lm] = wv.x; ws[lk + 1][lm] = wv.y;
        ws[lk + 2][lm] = wv.z; ws[lk + 3][lm] = wv.w;
        __syncthreads();

        #pragma unroll
        for (int q = 0; q < 16; q++) {
            float4 bv4 = *(float4*)&ws[q][c0];
            #pragma unroll
            for (int i = 0; i < 4; i++) {
                float a = as[r0 + i][q];
                acc[i][0] += a * bv4.x; acc[i][1] += a * bv4.y;
                acc[i][2] += a * bv4.z; acc[i][3] += a * bv4.w;
            }
        }
        __syncthreads();
    }

    float4 bb = *(const float4*)(bo + n0 + c0);
    #pragma unroll
    for (int i = 0; i < 4; i++) {
        float4 o;
        o.x = acc[i][0] + bb.x; o.y = acc[i][1] + bb.y;
        o.z = acc[i][2] + bb.z; o.w = acc[i][3] + bb.w;
        *(float4*)(out + (size_t)(m0 + r0 + i) * En + n0 + c0) = o;
    }
}

// ---------------------------------------------------------------------------
extern "C" void kernel_launch(void* const* d_in, const int* in_sizes, int n_in,
                              void* d_out, int out_size)
{
    const float* x  = (const float*)d_in[0];
    const float* Wq = (const float*)d_in[1];
    const float* bq = (const float*)d_in[2];
    const float* Wk = (const float*)d_in[3];
    const float* bk = (const float*)d_in[4];
    const float* Wv = (const float*)d_in[5];
    const float* bv = (const float*)d_in[6];
    const float* Wo = (const float*)d_in[7];
    const float* bo = (const float*)d_in[8];
    float* out = (float*)d_out;

    float* ctx;
    cudaGetSymbolAddress((void**)&ctx, g_ctx);

    qkv_kernel <<<dim3(Sn / 64, BHn, 3), 256>>>(x, Wq, bq, Wk, bk, Wv, bv);
    attn_kernel<<<dim3(Sn / 64, BHn),    256>>>(ctx);
    oproj_kernel<<<dim3(Mn / 64, En / 64), 256>>>(Wo, bo, out);
}